// round 14
// baseline (speedup 1.0000x reference)
#include <cuda_runtime.h>
#include <cuda_fp16.h>
#include <math_constants.h>
#include <cstdint>

// Problem constants (fixed by reference setup_inputs)
#define Nn   50000
#define Ee   800000
#define E2   (Ee + Nn)
#define Fdim 128
#define D1   256   // 4 heads x 64
#define D2   128   // 1 head x 128
#define D3   64    // GCN out
#define Bb   512
#define NCc  10
#define NB_SCAN ((Nn + 1023) / 1024)

typedef unsigned int u32;

// ---------------- scratch (device globals; no allocation allowed) -----------
__device__ __align__(16) int   g_deg[Nn];
__device__ __align__(16) int   g_rowstart[Nn + 1];
__device__ __align__(16) int   g_cursor[Nn];
__device__ __align__(16) int   g_col[E2];
__device__ __align__(16) int   g_partials[NB_SCAN + 1];

__device__ __align__(16) __half g_h1[(size_t)Nn * D1];
__device__ __align__(16) __half g_x1[(size_t)Nn * D1];
__device__ __align__(16) __half g_h2[(size_t)Nn * D2];
__device__ __align__(16) __half g_x2[(size_t)Nn * D2];
__device__ __align__(16) __half g_h3[(size_t)Nn * D3];
__device__ __align__(16) float  g_x3[(size_t)Nn * D3];
__device__ __align__(16) float  g_scs1[Nn * 4];
__device__ __align__(16) float  g_scd1[Nn * 4];
__device__ __align__(16) float  g_scs2[Nn];
__device__ __align__(16) float  g_scd2[Nn];
__device__ __align__(16) float  g_dis[Nn];
__device__ __align__(16) float  g_ws2[2 * 256];   // [0][c]=W2@a_src2, [1][c]=W2@a_dst2

// ---------------- small helpers ---------------------------------------------
__device__ __forceinline__ float lrelu(float v, float s) { return v > 0.f ? v : s * v; }

__device__ __forceinline__ u32 pack_half2(float x, float y) {
    __half2 h = __floats2half2_rn(x, y);
    return *(u32*)&h;
}

__device__ __forceinline__ float sel4(float4 v, int i) {
    float lo = (i & 1) ? v.y : v.x;
    float hi = (i & 1) ? v.w : v.z;
    return (i & 2) ? hi : lo;
}

__device__ __forceinline__ void pdl_wait() {
#if __CUDA_ARCH__ >= 900
    cudaGridDependencySynchronize();
#endif
}

__device__ __forceinline__ void mma_f16(float* c, const u32* a, const u32* b) {
    asm volatile(
        "mma.sync.aligned.m16n8k16.row.col.f32.f16.f16.f32 "
        "{%0,%1,%2,%3}, {%4,%5,%6,%7}, {%8,%9}, {%0,%1,%2,%3};"
        : "+f"(c[0]), "+f"(c[1]), "+f"(c[2]), "+f"(c[3])
        : "r"(a[0]), "r"(a[1]), "r"(a[2]), "r"(a[3]), "r"(b[0]), "r"(b[1]));
}

__device__ __forceinline__ int lbound(const int* __restrict__ a, int n, int key) {
    int l = 0, r = n;
    while (l < r) { int m = (l + r) >> 1; if (a[m] < key) l = m + 1; else r = m; }
    return l;
}

// ---------------- zero scs1/scd1 (for fused score accumulation) ---------------
__global__ void k_zero_sc(float* scs, float* scd, int n4) {
    int i = blockIdx.x * blockDim.x + threadIdx.x;
    if (i < n4) { scs[i] = 0.f; scd[i] = 0.f; }
}

// ---------------- init deg (+ block 0 computes ws2) ---------------------------
__global__ void k_init_deg_prep(int* deg, int n, const float* __restrict__ W2,
                                const float* __restrict__ as2,
                                const float* __restrict__ ad2,
                                float* __restrict__ ws2) {
    int i = blockIdx.x * blockDim.x + threadIdx.x;
    if (i < n) deg[i] = 1;  // self-loop
    if (blockIdx.x == 0) {
        for (int idx = threadIdx.x; idx < 512; idx += 256) {
            int f = idx & 255, o = idx >> 8;
            const float* a = (o == 0) ? as2 : ad2;
            float s = 0.f;
#pragma unroll 4
            for (int c = 0; c < 128; c++)
                s += W2[f * 128 + c] * a[c];
            ws2[o * 256 + f] = s;
        }
    }
}

// ---------------- CSR build --------------------------------------------------
__global__ void k_deg_scatter(const int* __restrict__ dst, int* deg, int e) {
    int i = blockIdx.x * blockDim.x + threadIdx.x;
    if (i < e) atomicAdd(&deg[dst[i]], 1);
}

__global__ void k_scan_block(const int* __restrict__ deg, int* __restrict__ rowstart,
                             int* __restrict__ partials, int n) {
    __shared__ int s[1024];
    int t = threadIdx.x;
    int gi = blockIdx.x * 1024 + t;
    int v = (gi < n) ? deg[gi] : 0;
    s[t] = v;
    __syncthreads();
#pragma unroll
    for (int off = 1; off < 1024; off <<= 1) {
        int xv = (t >= off) ? s[t - off] : 0;
        __syncthreads();
        s[t] += xv;
        __syncthreads();
    }
    if (gi < n) rowstart[gi] = s[t];          // block-inclusive
    if (t == 1023) partials[blockIdx.x] = s[t];
}

__global__ void k_scan_partials(int* partials, int* rowstart, int nb, int n) {
    __shared__ int wsum[2];
    int t = threadIdx.x;
    int lane = t & 31, w = t >> 5;
    int orig = (t < nb) ? partials[t] : 0;
    int v = orig;
#pragma unroll
    for (int o = 1; o < 32; o <<= 1) {
        int xv = __shfl_up_sync(0xffffffffu, v, o);
        if (lane >= o) v += xv;
    }
    if (lane == 31) wsum[w] = v;
    __syncthreads();
    if (w == 1) v += wsum[0];
    if (t < nb) partials[t] = v - orig;   // exclusive
    if (t == 63) rowstart[n] = v;         // total (= N + E)
}

// finalize scan + self-loop fill + GCN rsqrt(deg) in one pass
__global__ void k_scan_finalize_fill(const int* __restrict__ deg, int* __restrict__ rowstart,
                                     const int* __restrict__ partials, int* __restrict__ col,
                                     int* __restrict__ cursor, float* __restrict__ dis, int n) {
    int gi = blockIdx.x * 1024 + threadIdx.x;
    if (gi < n) {
        int d = deg[gi];
        int rs = rowstart[gi] - d + partials[blockIdx.x];
        rowstart[gi] = rs;
        col[rs] = gi;
        cursor[gi] = rs + 1;
        dis[gi] = rsqrtf((float)d);
    }
}

__global__ void k_scatter_edges(const int* __restrict__ src, const int* __restrict__ dst,
                                int* cursor, int* __restrict__ col, int e) {
    int i = blockIdx.x * blockDim.x + threadIdx.x;
    if (i < e) {
        int pos = atomicAdd(&cursor[dst[i]], 1);
        col[pos] = src[i];
    }
}

// ---------------- fp16 tensor-core GEMM (double-buffered smem, PDL-aware) ----
template <typename AT>
__global__ void __launch_bounds__(256) k_gemm_f16(const AT* __restrict__ A,
                                                  const float* __restrict__ B,
                                                  __half* __restrict__ C,
                                                  int M, int N, int K,
                                                  const float* __restrict__ a_srcv,
                                                  const float* __restrict__ a_dstv,
                                                  float* __restrict__ scs,
                                                  float* __restrict__ scd) {
    __shared__ u32 As[2][128][20];
    __shared__ u32 Bhi[2][64][20];

    pdl_wait();  // wait for producer (no-op when launched without PDL)

    int tid = threadIdx.x;
    int bm0 = blockIdx.x * 128, bn0 = blockIdx.y * 64;
    int w = tid >> 5, lane = tid & 31;
    int wm = (w & 3) * 32, wn = (w >> 2) * 32;
    int g = lane >> 2, t = lane & 3;

    float acc[2][4][4] = {};
    int niter = K >> 5;

    auto load_tile = [&](int buf, int kt) {
        if constexpr (sizeof(AT) == 4) {
            const float* Af = (const float*)A;
            int r = tid >> 1, cb = (tid & 1) * 16;
            bool ok = (bm0 + r) < M;
#pragma unroll
            for (int i = 0; i < 4; i++) {
                float4 v = make_float4(0.f, 0.f, 0.f, 0.f);
                if (ok) v = *(const float4*)(Af + (size_t)(bm0 + r) * K + kt + cb + 4 * i);
                As[buf][r][(cb >> 1) + 2 * i]     = pack_half2(v.x, v.y);
                As[buf][r][(cb >> 1) + 2 * i + 1] = pack_half2(v.z, v.w);
            }
        } else {
            const __half* Ah = (const __half*)A;
#pragma unroll
            for (int it = 0; it < 2; it++) {
                int idx = tid + it * 256;
                int r = idx >> 2, ch = (idx & 3) * 8;
                uint4 v = make_uint4(0u, 0u, 0u, 0u);
                if (bm0 + r < M) v = *(const uint4*)(Ah + (size_t)(bm0 + r) * K + kt + ch);
                As[buf][r][(ch >> 1) + 0] = v.x; As[buf][r][(ch >> 1) + 1] = v.y;
                As[buf][r][(ch >> 1) + 2] = v.z; As[buf][r][(ch >> 1) + 3] = v.w;
            }
        }
        {
            int r2 = tid >> 4;
            int c4 = (tid & 15) * 4;
            float4 v0 = *(const float4*)(B + (size_t)(kt + 2 * r2) * N + bn0 + c4);
            float4 v1 = *(const float4*)(B + (size_t)(kt + 2 * r2 + 1) * N + bn0 + c4);
            const float* p0 = &v0.x;
            const float* p1 = &v1.x;
#pragma unroll
            for (int i = 0; i < 4; i++)
                Bhi[buf][c4 + i][r2] = pack_half2(p0[i], p1[i]);
        }
    };

    load_tile(0, 0);
    __syncthreads();

    for (int it = 0; it < niter; it++) {
        int cur = it & 1;
        if (it + 1 < niter) load_tile(cur ^ 1, (it + 1) << 5);

#pragma unroll
        for (int kk = 0; kk < 2; kk++) {
            int kb = kk * 8;
            u32 af[2][4], bh[4][2];
#pragma unroll
            for (int mt = 0; mt < 2; mt++) {
                int r = wm + mt * 16 + g;
                af[mt][0] = As[cur][r][kb + t];       af[mt][1] = As[cur][r + 8][kb + t];
                af[mt][2] = As[cur][r][kb + 4 + t];   af[mt][3] = As[cur][r + 8][kb + 4 + t];
            }
#pragma unroll
            for (int nt = 0; nt < 4; nt++) {
                int c = wn + nt * 8 + g;
                bh[nt][0] = Bhi[cur][c][kb + t]; bh[nt][1] = Bhi[cur][c][kb + 4 + t];
            }
#pragma unroll
            for (int mt = 0; mt < 2; mt++)
#pragma unroll
                for (int nt = 0; nt < 4; nt++)
                    mma_f16(acc[mt][nt], af[mt], bh[nt]);
        }
        __syncthreads();
    }

#pragma unroll
    for (int mt = 0; mt < 2; mt++) {
        int r0 = bm0 + wm + mt * 16 + g;
#pragma unroll
        for (int nt = 0; nt < 4; nt++) {
            int c = bn0 + wn + nt * 8 + 2 * t;
            if (r0 < M)
                *(__half2*)(C + (size_t)r0 * N + c) =
                    __floats2half2_rn(acc[mt][nt][0], acc[mt][nt][1]);
            if (r0 + 8 < M)
                *(__half2*)(C + (size_t)(r0 + 8) * N + c) =
                    __floats2half2_rn(acc[mt][nt][2], acc[mt][nt][3]);
        }
    }

    // ---- fused GAT1 score partials (one head per 64-wide block column) ----
    if (a_srcv != nullptr) {
        int head = bn0 >> 6;
        float s_src[4] = {}, s_dst[4] = {};
#pragma unroll
        for (int mt = 0; mt < 2; mt++)
#pragma unroll
            for (int nt = 0; nt < 4; nt++) {
                int c0 = wn + nt * 8 + 2 * t;     // within [0,64)
                float a0s = a_srcv[head * 64 + c0], a1s = a_srcv[head * 64 + c0 + 1];
                float a0d = a_dstv[head * 64 + c0], a1d = a_dstv[head * 64 + c0 + 1];
                s_src[mt * 2 + 0] += acc[mt][nt][0] * a0s + acc[mt][nt][1] * a1s;
                s_src[mt * 2 + 1] += acc[mt][nt][2] * a0s + acc[mt][nt][3] * a1s;
                s_dst[mt * 2 + 0] += acc[mt][nt][0] * a0d + acc[mt][nt][1] * a1d;
                s_dst[mt * 2 + 1] += acc[mt][nt][2] * a0d + acc[mt][nt][3] * a1d;
            }
#pragma unroll
        for (int i = 0; i < 4; i++) {
            s_src[i] += __shfl_xor_sync(0xffffffffu, s_src[i], 1);
            s_src[i] += __shfl_xor_sync(0xffffffffu, s_src[i], 2);
            s_dst[i] += __shfl_xor_sync(0xffffffffu, s_dst[i], 1);
            s_dst[i] += __shfl_xor_sync(0xffffffffu, s_dst[i], 2);
        }
        if (t == 0) {
#pragma unroll
            for (int mt = 0; mt < 2; mt++) {
                int r0 = bm0 + wm + mt * 16 + g;
                if (r0 < M) {
                    atomicAdd(&scs[r0 * 4 + head], s_src[mt * 2]);
                    atomicAdd(&scd[r0 * 4 + head], s_dst[mt * 2]);
                }
                if (r0 + 8 < M) {
                    atomicAdd(&scs[(r0 + 8) * 4 + head], s_src[mt * 2 + 1]);
                    atomicAdd(&scd[(r0 + 8) * 4 + head], s_dst[mt * 2 + 1]);
                }
            }
        }
    }
}

// ---------------- GAT1 aggregation (+ fused GAT2 score epilogue) --------------
__global__ void k_gat_agg4(const __half* __restrict__ h, const float* __restrict__ scs,
                           const float* __restrict__ scd_arr,
                           const float* __restrict__ bias,
                           const float* __restrict__ bn_g, const float* __restrict__ bn_b,
                           const int* __restrict__ rowstart, const int* __restrict__ col,
                           const float* __restrict__ ws2,
                           __half* __restrict__ xout,
                           float* __restrict__ scs2, float* __restrict__ scd2, int n) {
    pdl_wait();
    int node = blockIdx.x * 8 + (threadIdx.x >> 5);
    int lane = threadIdx.x & 31;
    if (node >= n) return;
    int rs = rowstart[node], re = rowstart[node + 1];
    int hd = lane >> 3;

    float scd_h = scd_arr[node * 4 + hd];
    const uint4* hu = (const uint4*)h;          // row = 32 uint4
    const float4* scs4 = (const float4*)scs;

    float acc[8] = {};
    float ws = 0.f;

#define ACC_E4(sv, r)                                                          \
    {                                                                          \
        float wv = __expf(lrelu(sel4(sv, hd) + scd_h, 0.2f));                  \
        float2 f;                                                              \
        f = __half22float2(*(const __half2*)&(r).x); acc[0] += f.x * wv; acc[1] += f.y * wv; \
        f = __half22float2(*(const __half2*)&(r).y); acc[2] += f.x * wv; acc[3] += f.y * wv; \
        f = __half22float2(*(const __half2*)&(r).z); acc[4] += f.x * wv; acc[5] += f.y * wv; \
        f = __half22float2(*(const __half2*)&(r).w); acc[6] += f.x * wv; acc[7] += f.y * wv; \
        ws += wv;                                                              \
    }

    for (int base = rs; base < re; base += 32) {
        int idx = base + lane;
        int ck = col[idx < re ? idx : re - 1];
        int cnt = min(32, re - base);
        int j = 0;
        for (; j + 4 <= cnt; j += 4) {
            int s0 = __shfl_sync(0xffffffffu, ck, j + 0);
            int s1 = __shfl_sync(0xffffffffu, ck, j + 1);
            int s2 = __shfl_sync(0xffffffffu, ck, j + 2);
            int s3 = __shfl_sync(0xffffffffu, ck, j + 3);
            float4 sv0 = scs4[s0], sv1 = scs4[s1], sv2 = scs4[s2], sv3 = scs4[s3];
            uint4 r0 = hu[(size_t)s0 * 32 + lane];
            uint4 r1 = hu[(size_t)s1 * 32 + lane];
            uint4 r2 = hu[(size_t)s2 * 32 + lane];
            uint4 r3 = hu[(size_t)s3 * 32 + lane];
            ACC_E4(sv0, r0)
            ACC_E4(sv1, r1)
            ACC_E4(sv2, r2)
            ACC_E4(sv3, r3)
        }
        for (; j < cnt; j++) {
            int s = __shfl_sync(0xffffffffu, ck, j);
            float4 sv = scs4[s];
            uint4 r = hu[(size_t)s * 32 + lane];
            ACC_E4(sv, r)
        }
    }
#undef ACC_E4

    float inv = 1.f / ws;
    const float inv_bn = rsqrtf(1.0f + 1e-5f);
    float4 b0 = ((const float4*)bias)[2 * lane],  b1 = ((const float4*)bias)[2 * lane + 1];
    float4 g0 = ((const float4*)bn_g)[2 * lane],  g1 = ((const float4*)bn_g)[2 * lane + 1];
    float4 c0 = ((const float4*)bn_b)[2 * lane],  c1 = ((const float4*)bn_b)[2 * lane + 1];
    float o[8];
    o[0] = lrelu(acc[0] * inv + b0.x, 0.01f) * (g0.x * inv_bn) + c0.x;
    o[1] = lrelu(acc[1] * inv + b0.y, 0.01f) * (g0.y * inv_bn) + c0.y;
    o[2] = lrelu(acc[2] * inv + b0.z, 0.01f) * (g0.z * inv_bn) + c0.z;
    o[3] = lrelu(acc[3] * inv + b0.w, 0.01f) * (g0.w * inv_bn) + c0.w;
    o[4] = lrelu(acc[4] * inv + b1.x, 0.01f) * (g1.x * inv_bn) + c1.x;
    o[5] = lrelu(acc[5] * inv + b1.y, 0.01f) * (g1.y * inv_bn) + c1.y;
    o[6] = lrelu(acc[6] * inv + b1.z, 0.01f) * (g1.z * inv_bn) + c1.z;
    o[7] = lrelu(acc[7] * inv + b1.w, 0.01f) * (g1.w * inv_bn) + c1.w;
    uint4 p;
    p.x = pack_half2(o[0], o[1]); p.y = pack_half2(o[2], o[3]);
    p.z = pack_half2(o[4], o[5]); p.w = pack_half2(o[6], o[7]);
    ((uint4*)xout)[(size_t)node * 32 + lane] = p;

    // fused GAT2 scores
    float4 w0a = ((const float4*)ws2)[2 * lane],       w0b = ((const float4*)ws2)[2 * lane + 1];
    float4 w1a = ((const float4*)ws2)[64 + 2 * lane],  w1b = ((const float4*)ws2)[64 + 2 * lane + 1];
    float ss = o[0] * w0a.x + o[1] * w0a.y + o[2] * w0a.z + o[3] * w0a.w
             + o[4] * w0b.x + o[5] * w0b.y + o[6] * w0b.z + o[7] * w0b.w;
    float sd = o[0] * w1a.x + o[1] * w1a.y + o[2] * w1a.z + o[3] * w1a.w
             + o[4] * w1b.x + o[5] * w1b.y + o[6] * w1b.z + o[7] * w1b.w;
#pragma unroll
    for (int off = 16; off; off >>= 1) {
        ss += __shfl_xor_sync(0xffffffffu, ss, off);
        sd += __shfl_xor_sync(0xffffffffu, sd, off);
    }
    if (lane == 0) { scs2[node] = ss; scd2[node] = sd; }
}

// ---------------- GAT2 aggregation: 16-lane subgroups, 2 edges in flight -----
__global__ void k_gat_agg1(const __half* __restrict__ h, const float* __restrict__ scs,
                           const float* __restrict__ scd_arr,
                           const float* __restrict__ bias,
                           const float* __restrict__ bn_g, const float* __restrict__ bn_b,
                           const int* __restrict__ rowstart, const int* __restrict__ col,
                           __half* __restrict__ xout, int n) {
    pdl_wait();
    int node = blockIdx.x * 8 + (threadIdx.x >> 5);
    int lane = threadIdx.x & 31;
    if (node >= n) return;
    int rs = rowstart[node], re = rowstart[node + 1];
    int sub = lane >> 4, sl = lane & 15;

    float scd0 = scd_arr[node];
    const uint4* hu = (const uint4*)h;          // row = 16 uint4

    float acc[8] = {};
    float ws = 0.f;

#define ACC_E1(e, r)                                                           \
    {                                                                          \
        float wv = __expf(lrelu((e) + scd0, 0.2f));                            \
        float2 f;                                                              \
        f = __half22float2(*(const __half2*)&(r).x); acc[0] += f.x * wv; acc[1] += f.y * wv; \
        f = __half22float2(*(const __half2*)&(r).y); acc[2] += f.x * wv; acc[3] += f.y * wv; \
        f = __half22float2(*(const __half2*)&(r).z); acc[4] += f.x * wv; acc[5] += f.y * wv; \
        f = __half22float2(*(const __half2*)&(r).w); acc[6] += f.x * wv; acc[7] += f.y * wv; \
        ws += wv;                                                              \
    }

    for (int base = rs; base < re; base += 32) {
        int idx = base + lane;
        int ck = col[idx < re ? idx : re - 1];
        int cnt = min(32, re - base);
        int j = 0;
        for (; j + 4 <= cnt; j += 4) {
            int sa = __shfl_sync(0xffffffffu, ck, j + sub);
            int sb = __shfl_sync(0xffffffffu, ck, j + 2 + sub);
            float ea = scs[sa], eb = scs[sb];
            uint4 ra = hu[(size_t)sa * 16 + sl];
            uint4 rb = hu[(size_t)sb * 16 + sl];
            ACC_E1(ea, ra)
            ACC_E1(eb, rb)
        }
        for (; j < cnt; j++) {
            int s = __shfl_sync(0xffffffffu, ck, j);
            if ((j & 1) == sub) {
                float e = scs[s];
                uint4 r = hu[(size_t)s * 16 + sl];
                ACC_E1(e, r)
            }
        }
    }
#undef ACC_E1

#pragma unroll
    for (int i = 0; i < 8; i++) acc[i] += __shfl_xor_sync(0xffffffffu, acc[i], 16);
    ws += __shfl_xor_sync(0xffffffffu, ws, 16);

    float inv = 1.f / ws;
    const float inv_bn = rsqrtf(1.0f + 1e-5f);
    float4 b0 = ((const float4*)bias)[2 * sl],  b1 = ((const float4*)bias)[2 * sl + 1];
    float4 g0 = ((const float4*)bn_g)[2 * sl],  g1 = ((const float4*)bn_g)[2 * sl + 1];
    float4 c0 = ((const float4*)bn_b)[2 * sl],  c1 = ((const float4*)bn_b)[2 * sl + 1];
    float o[8];
    o[0] = lrelu(acc[0] * inv + b0.x, 0.01f) * (g0.x * inv_bn) + c0.x;
    o[1] = lrelu(acc[1] * inv + b0.y, 0.01f) * (g0.y * inv_bn) + c0.y;
    o[2] = lrelu(acc[2] * inv + b0.z, 0.01f) * (g0.z * inv_bn) + c0.z;
    o[3] = lrelu(acc[3] * inv + b0.w, 0.01f) * (g0.w * inv_bn) + c0.w;
    o[4] = lrelu(acc[4] * inv + b1.x, 0.01f) * (g1.x * inv_bn) + c1.x;
    o[5] = lrelu(acc[5] * inv + b1.y, 0.01f) * (g1.y * inv_bn) + c1.y;
    o[6] = lrelu(acc[6] * inv + b1.z, 0.01f) * (g1.z * inv_bn) + c1.z;
    o[7] = lrelu(acc[7] * inv + b1.w, 0.01f) * (g1.w * inv_bn) + c1.w;
    if (sub == 0) {
        uint4 p;
        p.x = pack_half2(o[0], o[1]); p.y = pack_half2(o[2], o[3]);
        p.z = pack_half2(o[4], o[5]); p.w = pack_half2(o[6], o[7]);
        ((uint4*)xout)[(size_t)node * 16 + sl] = p;
    }
}

// ---------------- GCN aggregation: 8-lane subgroups, 4 edges in flight -------
__global__ void k_gcn_agg(const __half* __restrict__ h, const float* __restrict__ dis,
                          const float* __restrict__ bg,
                          const int* __restrict__ rowstart, const int* __restrict__ col,
                          float* __restrict__ xout, int n) {
    pdl_wait();
    int node = blockIdx.x * 8 + (threadIdx.x >> 5);
    int lane = threadIdx.x & 31;
    if (node >= n) return;
    int rs = rowstart[node], re = rowstart[node + 1];
    int sub = lane >> 3, sl = lane & 7;
    float wi = dis[node];
    const uint4* hu = (const uint4*)h;          // row = 8 uint4

    float acc[8] = {};

#define ACC_G(wv, r)                                                           \
    {                                                                          \
        float2 f;                                                              \
        f = __half22float2(*(const __half2*)&(r).x); acc[0] += f.x * (wv); acc[1] += f.y * (wv); \
        f = __half22float2(*(const __half2*)&(r).y); acc[2] += f.x * (wv); acc[3] += f.y * (wv); \
        f = __half22float2(*(const __half2*)&(r).z); acc[4] += f.x * (wv); acc[5] += f.y * (wv); \
        f = __half22float2(*(const __half2*)&(r).w); acc[6] += f.x * (wv); acc[7] += f.y * (wv); \
    }

    for (int base = rs; base < re; base += 32) {
        int idx = base + lane;
        int ck = col[idx < re ? idx : re - 1];
        int cnt = min(32, re - base);
        int j = 0;
        for (; j + 4 <= cnt; j += 4) {
            int s = __shfl_sync(0xffffffffu, ck, j + sub);
            float w = dis[s] * wi;
            uint4 r = hu[(size_t)s * 8 + sl];
            ACC_G(w, r)
        }
        for (; j < cnt; j++) {
            int s = __shfl_sync(0xffffffffu, ck, j);
            if ((j & 3) == sub) {
                float w = dis[s] * wi;
                uint4 r = hu[(size_t)s * 8 + sl];
                ACC_G(w, r)
            }
        }
    }
#undef ACC_G

#pragma unroll
    for (int i = 0; i < 8; i++) {
        acc[i] += __shfl_xor_sync(0xffffffffu, acc[i], 8);
        acc[i] += __shfl_xor_sync(0xffffffffu, acc[i], 16);
    }

    if (sub == 0) {
        float4 bg0 = ((const float4*)bg)[2 * sl], bg1 = ((const float4*)bg)[2 * sl + 1];
        float4 o0, o1;
        o0.x = lrelu(acc[0] + bg0.x, 0.01f); o0.y = lrelu(acc[1] + bg0.y, 0.01f);
        o0.z = lrelu(acc[2] + bg0.z, 0.01f); o0.w = lrelu(acc[3] + bg0.w, 0.01f);
        o1.x = lrelu(acc[4] + bg1.x, 0.01f); o1.y = lrelu(acc[5] + bg1.y, 0.01f);
        o1.z = lrelu(acc[6] + bg1.z, 0.01f); o1.w = lrelu(acc[7] + bg1.w, 0.01f);
        ((float4*)xout)[(size_t)node * 16 + 2 * sl]     = o0;
        ((float4*)xout)[(size_t)node * 16 + 2 * sl + 1] = o1;
    }
}

// ---------------- fused pool (segment sum) + MLP ------------------------------
__global__ void __launch_bounds__(128) k_pool_mlp(const float* __restrict__ x3,
                                                  const int* __restrict__ batch,
                                                  const float* __restrict__ l1W,
                                                  const float* __restrict__ l1b,
                                                  const float* __restrict__ g3,
                                                  const float* __restrict__ b3,
                                                  const float* __restrict__ l2W,
                                                  const float* __restrict__ l2b,
                                                  float* __restrict__ out) {
    pdl_wait();
    int b = blockIdx.x;
    int t = threadIdx.x;
    __shared__ int seg[2];
    __shared__ float sp2[2][64];
    __shared__ float spool[64];
    __shared__ float sy[128];

    if (t < 2) seg[t] = lbound(batch, Nn, b + t);
    __syncthreads();
    int lo = seg[0], hi = seg[1];

    int ch = t & 63, half = t >> 6;
    float s = 0.f;
    for (int node = lo + half; node < hi; node += 2)
        s += x3[(size_t)node * D3 + ch];
    sp2[half][ch] = s;
    __syncthreads();
    if (t < 64) {
        float cnt = fmaxf((float)(hi - lo), 1.f);
        spool[t] = (sp2[0][t] + sp2[1][t]) / cnt;
    }
    __syncthreads();

    float v = l1b[t];
#pragma unroll
    for (int k = 0; k < 64; k++) v += spool[k] * l1W[k * 128 + t];
    v = v * (g3[t] * rsqrtf(1.0f + 1e-5f)) + b3[t];
    v = lrelu(v, 0.01f);
    sy[t] = v;
    __syncthreads();
    if (t < NCc) {
        float o = l2b[t];
#pragma unroll
        for (int k = 0; k < 128; k++) o += sy[k] * l2W[k * NCc + t];
        out[b * NCc + t] = o;
    }
}

// ---------------- PDL launch helper -------------------------------------------
template <typename Kern, typename... Args>
static inline void launch_pdl(Kern kern, dim3 grid, dim3 block, Args... args) {
    cudaLaunchConfig_t cfg = {};
    cfg.gridDim = grid;
    cfg.blockDim = block;
    cfg.dynamicSmemBytes = 0;
    cfg.stream = 0;
    cudaLaunchAttribute attr[1];
    attr[0].id = cudaLaunchAttributeProgrammaticStreamSerialization;
    attr[0].val.programmaticStreamSerializationAllowed = 1;
    cfg.attrs = attr;
    cfg.numAttrs = 1;
    cudaLaunchKernelEx(&cfg, kern, args...);
}

// ---------------- launch -----------------------------------------------------
extern "C" void kernel_launch(void* const* d_in, const int* in_sizes, int n_in,
                              void* d_out, int out_size) {
    const float* x      = (const float*)d_in[0];
    const int*   ei     = (const int*)d_in[1];
    const int*   batch  = (const int*)d_in[2];
    const float* W1     = (const float*)d_in[3];
    const float* a_src1 = (const float*)d_in[4];
    const float* a_dst1 = (const float*)d_in[5];
    const float* b1     = (const float*)d_in[6];
    const float* W2     = (const float*)d_in[7];
    const float* a_src2 = (const float*)d_in[8];
    const float* a_dst2 = (const float*)d_in[9];
    const float* b2     = (const float*)d_in[10];
    const float* Wg     = (const float*)d_in[11];
    const float* bg     = (const float*)d_in[12];
    const float* bn1g   = (const float*)d_in[13];
    const float* bn1b   = (const float*)d_in[14];
    const float* bn2g   = (const float*)d_in[15];
    const float* bn2b   = (const float*)d_in[16];
    const float* bn3g   = (const float*)d_in[17];
    const float* bn3b   = (const float*)d_in[18];
    const float* l1W    = (const float*)d_in[19];
    const float* l1b    = (const float*)d_in[20];
    const float* l2W    = (const float*)d_in[21];
    const float* l2b    = (const float*)d_in[22];
    float* out = (float*)d_out;

    int *deg, *rowstart, *cursor, *col, *partials;
    __half *h1, *h2, *h3, *x1, *x2;
    float *x3, *scs1, *scd1, *scs2, *scd2, *dis, *ws2;
    cudaGetSymbolAddress((void**)&deg, g_deg);
    cudaGetSymbolAddress((void**)&rowstart, g_rowstart);
    cudaGetSymbolAddress((void**)&cursor, g_cursor);
    cudaGetSymbolAddress((void**)&col, g_col);
    cudaGetSymbolAddress((void**)&partials, g_partials);
    cudaGetSymbolAddress((void**)&h1, g_h1);
    cudaGetSymbolAddress((void**)&x1, g_x1);
    cudaGetSymbolAddress((void**)&h2, g_h2);
    cudaGetSymbolAddress((void**)&x2, g_x2);
    cudaGetSymbolAddress((void**)&h3, g_h3);
    cudaGetSymbolAddress((void**)&x3, g_x3);
    cudaGetSymbolAddress((void**)&scs1, g_scs1);
    cudaGetSymbolAddress((void**)&scd1, g_scd1);
    cudaGetSymbolAddress((void**)&scs2, g_scs2);
    cudaGetSymbolAddress((void**)&scd2, g_scd2);
    cudaGetSymbolAddress((void**)&dis, g_dis);
    cudaGetSymbolAddress((void**)&ws2, g_ws2);

    const int* src = ei;
    const int* dst = ei + Ee;

    static cudaStream_t s2 = nullptr;
    static cudaEvent_t evFork = nullptr, evJoin = nullptr;
    if (!s2) {
        cudaStreamCreateWithFlags(&s2, cudaStreamNonBlocking);
        cudaEventCreateWithFlags(&evFork, cudaEventDisableTiming);
        cudaEventCreateWithFlags(&evJoin, cudaEventDisableTiming);
    }

    // ---- fork ----
    cudaEventRecord(evFork, 0);
    cudaStreamWaitEvent(s2, evFork, 0);

    // s0: zero score buffers (needed by gemm1's fused epilogue)
    k_zero_sc<<<(Nn * 4 + 255) / 256, 256>>>(scs1, scd1, Nn * 4);

    // s2: CSR chain
    k_init_deg_prep<<<(Nn + 255) / 256, 256, 0, s2>>>(deg, Nn, W2, a_src2, a_dst2, ws2);
    k_deg_scatter<<<(Ee + 255) / 256, 256, 0, s2>>>(dst, deg, Ee);
    k_scan_block<<<NB_SCAN, 1024, 0, s2>>>(deg, rowstart, partials, Nn);
    k_scan_partials<<<1, 64, 0, s2>>>(partials, rowstart, NB_SCAN, Nn);
    k_scan_finalize_fill<<<NB_SCAN, 1024, 0, s2>>>(deg, rowstart, partials, col, cursor, dis, Nn);
    k_scatter_edges<<<(Ee + 255) / 256, 256, 0, s2>>>(src, dst, cursor, col, Ee);
    cudaEventRecord(evJoin, s2);

    // s0: GEMM1 (+fused GAT1 scores); PDL vs the zero-fill
    launch_pdl(k_gemm_f16<float>, dim3((Nn + 127) / 128, D1 / 64), dim3(256),
               x, W1, h1, (int)Nn, (int)D1, (int)Fdim, a_src1, a_dst1, scs1, scd1);

    cudaStreamWaitEvent(0, evJoin, 0);

    // ---- GAT layer 1 aggregation (also emits GAT2 scores); after event: plain
    k_gat_agg4<<<(Nn + 7) / 8, 256>>>(h1, scs1, scd1, b1, bn1g, bn1b,
                                      rowstart, col, ws2, x1, scs2, scd2, Nn);

    // ---- GAT layer 2 (PDL chain from here) ----
    launch_pdl(k_gemm_f16<__half>, dim3((Nn + 127) / 128, D2 / 64), dim3(256),
               x1, W2, h2, (int)Nn, (int)D2, (int)D1,
               (const float*)nullptr, (const float*)nullptr,
               (float*)nullptr, (float*)nullptr);
    launch_pdl(k_gat_agg1, dim3((Nn + 7) / 8), dim3(256),
               (const __half*)h2, (const float*)scs2, (const float*)scd2, b2, bn2g, bn2b,
               (const int*)rowstart, (const int*)col, x2, (int)Nn);

    // ---- GCN ----
    launch_pdl(k_gemm_f16<__half>, dim3((Nn + 127) / 128, D3 / 64), dim3(256),
               x2, Wg, h3, (int)Nn, (int)D3, (int)D2,
               (const float*)nullptr, (const float*)nullptr,
               (float*)nullptr, (float*)nullptr);
    launch_pdl(k_gcn_agg, dim3((Nn + 7) / 8), dim3(256),
               (const __half*)h3, (const float*)dis, bg,
               (const int*)rowstart, (const int*)col, x3, (int)Nn);

    // ---- fused global mean pool + MLP head ----
    launch_pdl(k_pool_mlp, dim3(Bb), dim3(128),
               (const float*)x3, batch, l1W, l1b, bn3g, bn3b, l2W, l2b, out);
}

// round 15
// speedup vs baseline: 1.1162x; 1.1162x over previous
#include <cuda_runtime.h>
#include <cuda_fp16.h>
#include <math_constants.h>
#include <cstdint>

// Problem constants (fixed by reference setup_inputs)
#define Nn   50000
#define Ee   800000
#define E2   (Ee + Nn)
#define Fdim 128
#define D1   256   // 4 heads x 64
#define D2   128   // 1 head x 128
#define D3   64    // GCN out
#define Bb   512
#define NCc  10
#define NB_SCAN ((Nn + 1023) / 1024)

typedef unsigned int u32;

// ---------------- scratch (device globals; no allocation allowed) -----------
__device__ __align__(16) int   g_deg[Nn];
__device__ __align__(16) int   g_rowstart[Nn + 1];
__device__ __align__(16) int   g_cursor[Nn];
__device__ __align__(16) int   g_col[E2];
__device__ __align__(16) int   g_partials[NB_SCAN + 1];

__device__ __align__(16) __half g_h1[(size_t)Nn * D1];
__device__ __align__(16) __half g_x1[(size_t)Nn * D1];
__device__ __align__(16) __half g_h2[(size_t)Nn * D2];
__device__ __align__(16) __half g_x2[(size_t)Nn * D2];
__device__ __align__(16) __half g_h3[(size_t)Nn * D3];
__device__ __align__(16) float  g_x3[(size_t)Nn * D3];
__device__ __align__(16) float  g_scs1[Nn * 4];
__device__ __align__(16) float  g_scd1[Nn * 4];
__device__ __align__(16) float  g_scs2[Nn];
__device__ __align__(16) float  g_scd2[Nn];
__device__ __align__(16) float  g_dis[Nn];
__device__ __align__(16) float  g_ws2[2 * 256];   // [0][c]=W2@a_src2, [1][c]=W2@a_dst2

// ---------------- small helpers ---------------------------------------------
__device__ __forceinline__ float lrelu(float v, float s) { return v > 0.f ? v : s * v; }

__device__ __forceinline__ u32 pack_half2(float x, float y) {
    __half2 h = __floats2half2_rn(x, y);
    return *(u32*)&h;
}

__device__ __forceinline__ float sel4(float4 v, int i) {
    float lo = (i & 1) ? v.y : v.x;
    float hi = (i & 1) ? v.w : v.z;
    return (i & 2) ? hi : lo;
}

__device__ __forceinline__ void mma_f16(float* c, const u32* a, const u32* b) {
    asm volatile(
        "mma.sync.aligned.m16n8k16.row.col.f32.f16.f16.f32 "
        "{%0,%1,%2,%3}, {%4,%5,%6,%7}, {%8,%9}, {%0,%1,%2,%3};"
        : "+f"(c[0]), "+f"(c[1]), "+f"(c[2]), "+f"(c[3])
        : "r"(a[0]), "r"(a[1]), "r"(a[2]), "r"(a[3]), "r"(b[0]), "r"(b[1]));
}

__device__ __forceinline__ int lbound(const int* __restrict__ a, int n, int key) {
    int l = 0, r = n;
    while (l < r) { int m = (l + r) >> 1; if (a[m] < key) l = m + 1; else r = m; }
    return l;
}

// ---------------- init deg (+ block 0 computes ws2) ---------------------------
__global__ void k_init_deg_prep(int* deg, int n, const float* __restrict__ W2,
                                const float* __restrict__ as2,
                                const float* __restrict__ ad2,
                                float* __restrict__ ws2) {
    int i = blockIdx.x * blockDim.x + threadIdx.x;
    if (i < n) deg[i] = 1;  // self-loop
    if (blockIdx.x == 0) {
        for (int idx = threadIdx.x; idx < 512; idx += 256) {
            int f = idx & 255, o = idx >> 8;
            const float* a = (o == 0) ? as2 : ad2;
            float s = 0.f;
#pragma unroll 4
            for (int c = 0; c < 128; c++)
                s += W2[f * 128 + c] * a[c];
            ws2[o * 256 + f] = s;
        }
    }
}

// ---------------- CSR build --------------------------------------------------
__global__ void k_deg_scatter(const int* __restrict__ dst, int* deg, int e) {
    int i = blockIdx.x * blockDim.x + threadIdx.x;
    if (i < e) atomicAdd(&deg[dst[i]], 1);
}

__global__ void k_scan_block(const int* __restrict__ deg, int* __restrict__ rowstart,
                             int* __restrict__ partials, int n) {
    __shared__ int s[1024];
    int t = threadIdx.x;
    int gi = blockIdx.x * 1024 + t;
    int v = (gi < n) ? deg[gi] : 0;
    s[t] = v;
    __syncthreads();
#pragma unroll
    for (int off = 1; off < 1024; off <<= 1) {
        int xv = (t >= off) ? s[t - off] : 0;
        __syncthreads();
        s[t] += xv;
        __syncthreads();
    }
    if (gi < n) rowstart[gi] = s[t];          // block-inclusive
    if (t == 1023) partials[blockIdx.x] = s[t];
}

__global__ void k_scan_partials(int* partials, int* rowstart, int nb, int n) {
    __shared__ int wsum[2];
    int t = threadIdx.x;
    int lane = t & 31, w = t >> 5;
    int orig = (t < nb) ? partials[t] : 0;
    int v = orig;
#pragma unroll
    for (int o = 1; o < 32; o <<= 1) {
        int xv = __shfl_up_sync(0xffffffffu, v, o);
        if (lane >= o) v += xv;
    }
    if (lane == 31) wsum[w] = v;
    __syncthreads();
    if (w == 1) v += wsum[0];
    if (t < nb) partials[t] = v - orig;   // exclusive
    if (t == 63) rowstart[n] = v;         // total (= N + E)
}

// finalize scan + self-loop fill + GCN rsqrt(deg) in one pass
__global__ void k_scan_finalize_fill(const int* __restrict__ deg, int* __restrict__ rowstart,
                                     const int* __restrict__ partials, int* __restrict__ col,
                                     int* __restrict__ cursor, float* __restrict__ dis, int n) {
    int gi = blockIdx.x * 1024 + threadIdx.x;
    if (gi < n) {
        int d = deg[gi];
        int rs = rowstart[gi] - d + partials[blockIdx.x];
        rowstart[gi] = rs;
        col[rs] = gi;
        cursor[gi] = rs + 1;
        dis[gi] = rsqrtf((float)d);
    }
}

__global__ void k_scatter_edges(const int* __restrict__ src, const int* __restrict__ dst,
                                int* cursor, int* __restrict__ col, int e) {
    int i = blockIdx.x * blockDim.x + threadIdx.x;
    if (i < e) {
        int pos = atomicAdd(&cursor[dst[i]], 1);
        col[pos] = src[i];
    }
}

// ---------------- fp16 tensor-core GEMM (double-buffered smem) ---------------
// Optional fused GAT1-score epilogue (atomic-free): within a block each
// (row, head) gets contributions from exactly warps (w, w+4); warps 0-3 stash
// partials in smem, warps 4-7 add and store.
template <typename AT>
__global__ void __launch_bounds__(256) k_gemm_f16(const AT* __restrict__ A,
                                                  const float* __restrict__ B,
                                                  __half* __restrict__ C,
                                                  int M, int N, int K,
                                                  const float* __restrict__ a_srcv,
                                                  const float* __restrict__ a_dstv,
                                                  float* __restrict__ scs,
                                                  float* __restrict__ scd) {
    __shared__ u32 As[2][128][20];
    __shared__ u32 Bhi[2][64][20];
    __shared__ float red_s[4][32], red_d[4][32];

    int tid = threadIdx.x;
    int bm0 = blockIdx.x * 128, bn0 = blockIdx.y * 64;
    int w = tid >> 5, lane = tid & 31;
    int wm = (w & 3) * 32, wn = (w >> 2) * 32;
    int g = lane >> 2, t = lane & 3;

    float acc[2][4][4] = {};
    int niter = K >> 5;

    auto load_tile = [&](int buf, int kt) {
        if constexpr (sizeof(AT) == 4) {
            const float* Af = (const float*)A;
            int r = tid >> 1, cb = (tid & 1) * 16;
            bool ok = (bm0 + r) < M;
#pragma unroll
            for (int i = 0; i < 4; i++) {
                float4 v = make_float4(0.f, 0.f, 0.f, 0.f);
                if (ok) v = *(const float4*)(Af + (size_t)(bm0 + r) * K + kt + cb + 4 * i);
                As[buf][r][(cb >> 1) + 2 * i]     = pack_half2(v.x, v.y);
                As[buf][r][(cb >> 1) + 2 * i + 1] = pack_half2(v.z, v.w);
            }
        } else {
            const __half* Ah = (const __half*)A;
#pragma unroll
            for (int it = 0; it < 2; it++) {
                int idx = tid + it * 256;
                int r = idx >> 2, ch = (idx & 3) * 8;
                uint4 v = make_uint4(0u, 0u, 0u, 0u);
                if (bm0 + r < M) v = *(const uint4*)(Ah + (size_t)(bm0 + r) * K + kt + ch);
                As[buf][r][(ch >> 1) + 0] = v.x; As[buf][r][(ch >> 1) + 1] = v.y;
                As[buf][r][(ch >> 1) + 2] = v.z; As[buf][r][(ch >> 1) + 3] = v.w;
            }
        }
        {
            int r2 = tid >> 4;
            int c4 = (tid & 15) * 4;
            float4 v0 = *(const float4*)(B + (size_t)(kt + 2 * r2) * N + bn0 + c4);
            float4 v1 = *(const float4*)(B + (size_t)(kt + 2 * r2 + 1) * N + bn0 + c4);
            const float* p0 = &v0.x;
            const float* p1 = &v1.x;
#pragma unroll
            for (int i = 0; i < 4; i++)
                Bhi[buf][c4 + i][r2] = pack_half2(p0[i], p1[i]);
        }
    };

    load_tile(0, 0);
    __syncthreads();

    for (int it = 0; it < niter; it++) {
        int cur = it & 1;
        if (it + 1 < niter) load_tile(cur ^ 1, (it + 1) << 5);

#pragma unroll
        for (int kk = 0; kk < 2; kk++) {
            int kb = kk * 8;
            u32 af[2][4], bh[4][2];
#pragma unroll
            for (int mt = 0; mt < 2; mt++) {
                int r = wm + mt * 16 + g;
                af[mt][0] = As[cur][r][kb + t];       af[mt][1] = As[cur][r + 8][kb + t];
                af[mt][2] = As[cur][r][kb + 4 + t];   af[mt][3] = As[cur][r + 8][kb + 4 + t];
            }
#pragma unroll
            for (int nt = 0; nt < 4; nt++) {
                int c = wn + nt * 8 + g;
                bh[nt][0] = Bhi[cur][c][kb + t]; bh[nt][1] = Bhi[cur][c][kb + 4 + t];
            }
#pragma unroll
            for (int mt = 0; mt < 2; mt++)
#pragma unroll
                for (int nt = 0; nt < 4; nt++)
                    mma_f16(acc[mt][nt], af[mt], bh[nt]);
        }
        __syncthreads();
    }

#pragma unroll
    for (int mt = 0; mt < 2; mt++) {
        int r0 = bm0 + wm + mt * 16 + g;
#pragma unroll
        for (int nt = 0; nt < 4; nt++) {
            int c = bn0 + wn + nt * 8 + 2 * t;
            if (r0 < M)
                *(__half2*)(C + (size_t)r0 * N + c) =
                    __floats2half2_rn(acc[mt][nt][0], acc[mt][nt][1]);
            if (r0 + 8 < M)
                *(__half2*)(C + (size_t)(r0 + 8) * N + c) =
                    __floats2half2_rn(acc[mt][nt][2], acc[mt][nt][3]);
        }
    }

    // ---- fused GAT1 score epilogue (atomic-free) ----
    if (a_srcv != nullptr) {
        int head = bn0 >> 6;
        float s_src[4] = {}, s_dst[4] = {};
#pragma unroll
        for (int mt = 0; mt < 2; mt++)
#pragma unroll
            for (int nt = 0; nt < 4; nt++) {
                int c0 = wn + nt * 8 + 2 * t;     // within [0,64)
                float a0s = a_srcv[head * 64 + c0], a1s = a_srcv[head * 64 + c0 + 1];
                float a0d = a_dstv[head * 64 + c0], a1d = a_dstv[head * 64 + c0 + 1];
                s_src[mt * 2 + 0] += acc[mt][nt][0] * a0s + acc[mt][nt][1] * a1s;
                s_src[mt * 2 + 1] += acc[mt][nt][2] * a0s + acc[mt][nt][3] * a1s;
                s_dst[mt * 2 + 0] += acc[mt][nt][0] * a0d + acc[mt][nt][1] * a1d;
                s_dst[mt * 2 + 1] += acc[mt][nt][2] * a0d + acc[mt][nt][3] * a1d;
            }
#pragma unroll
        for (int i = 0; i < 4; i++) {
            s_src[i] += __shfl_xor_sync(0xffffffffu, s_src[i], 1);
            s_src[i] += __shfl_xor_sync(0xffffffffu, s_src[i], 2);
            s_dst[i] += __shfl_xor_sync(0xffffffffu, s_dst[i], 1);
            s_dst[i] += __shfl_xor_sync(0xffffffffu, s_dst[i], 2);
        }
        // local row ids within this warp's 32-row chunk: i=0->g, 1->g+8, 2->16+g, 3->24+g
        if (w < 4 && t == 0) {
            red_s[w][g]      = s_src[0]; red_s[w][g + 8]  = s_src[1];
            red_s[w][g + 16] = s_src[2]; red_s[w][g + 24] = s_src[3];
            red_d[w][g]      = s_dst[0]; red_d[w][g + 8]  = s_dst[1];
            red_d[w][g + 16] = s_dst[2]; red_d[w][g + 24] = s_dst[3];
        }
        __syncthreads();
        if (w >= 4 && t == 0) {
            int wq = w - 4;
            int lr[4] = {g, g + 8, g + 16, g + 24};
#pragma unroll
            for (int i = 0; i < 4; i++) {
                int r0 = bm0 + wq * 32 + lr[i];
                if (r0 < M) {
                    scs[r0 * 4 + head] = red_s[wq][lr[i]] + s_src[i];
                    scd[r0 * 4 + head] = red_d[wq][lr[i]] + s_dst[i];
                }
            }
        }
    }
}

// ---------------- GAT1 aggregation (+ fused GAT2 score epilogue) --------------
__global__ void k_gat_agg4(const __half* __restrict__ h, const float* __restrict__ scs,
                           const float* __restrict__ scd_arr,
                           const float* __restrict__ bias,
                           const float* __restrict__ bn_g, const float* __restrict__ bn_b,
                           const int* __restrict__ rowstart, const int* __restrict__ col,
                           const float* __restrict__ ws2,
                           __half* __restrict__ xout,
                           float* __restrict__ scs2, float* __restrict__ scd2, int n) {
    int node = blockIdx.x * 8 + (threadIdx.x >> 5);
    int lane = threadIdx.x & 31;
    if (node >= n) return;
    int rs = rowstart[node], re = rowstart[node + 1];
    int hd = lane >> 3;

    float scd_h = scd_arr[node * 4 + hd];
    const uint4* hu = (const uint4*)h;          // row = 32 uint4
    const float4* scs4 = (const float4*)scs;

    float acc[8] = {};
    float ws = 0.f;

#define ACC_E4(sv, r)                                                          \
    {                                                                          \
        float wv = __expf(lrelu(sel4(sv, hd) + scd_h, 0.2f));                  \
        float2 f;                                                              \
        f = __half22float2(*(const __half2*)&(r).x); acc[0] += f.x * wv; acc[1] += f.y * wv; \
        f = __half22float2(*(const __half2*)&(r).y); acc[2] += f.x * wv; acc[3] += f.y * wv; \
        f = __half22float2(*(const __half2*)&(r).z); acc[4] += f.x * wv; acc[5] += f.y * wv; \
        f = __half22float2(*(const __half2*)&(r).w); acc[6] += f.x * wv; acc[7] += f.y * wv; \
        ws += wv;                                                              \
    }

    for (int base = rs; base < re; base += 32) {
        int idx = base + lane;
        int ck = col[idx < re ? idx : re - 1];
        int cnt = min(32, re - base);
        int j = 0;
        for (; j + 4 <= cnt; j += 4) {
            int s0 = __shfl_sync(0xffffffffu, ck, j + 0);
            int s1 = __shfl_sync(0xffffffffu, ck, j + 1);
            int s2 = __shfl_sync(0xffffffffu, ck, j + 2);
            int s3 = __shfl_sync(0xffffffffu, ck, j + 3);
            float4 sv0 = scs4[s0], sv1 = scs4[s1], sv2 = scs4[s2], sv3 = scs4[s3];
            uint4 r0 = hu[(size_t)s0 * 32 + lane];
            uint4 r1 = hu[(size_t)s1 * 32 + lane];
            uint4 r2 = hu[(size_t)s2 * 32 + lane];
            uint4 r3 = hu[(size_t)s3 * 32 + lane];
            ACC_E4(sv0, r0)
            ACC_E4(sv1, r1)
            ACC_E4(sv2, r2)
            ACC_E4(sv3, r3)
        }
        for (; j < cnt; j++) {
            int s = __shfl_sync(0xffffffffu, ck, j);
            float4 sv = scs4[s];
            uint4 r = hu[(size_t)s * 32 + lane];
            ACC_E4(sv, r)
        }
    }
#undef ACC_E4

    float inv = 1.f / ws;
    const float inv_bn = rsqrtf(1.0f + 1e-5f);
    float4 b0 = ((const float4*)bias)[2 * lane],  b1 = ((const float4*)bias)[2 * lane + 1];
    float4 g0 = ((const float4*)bn_g)[2 * lane],  g1 = ((const float4*)bn_g)[2 * lane + 1];
    float4 c0 = ((const float4*)bn_b)[2 * lane],  c1 = ((const float4*)bn_b)[2 * lane + 1];
    float o[8];
    o[0] = lrelu(acc[0] * inv + b0.x, 0.01f) * (g0.x * inv_bn) + c0.x;
    o[1] = lrelu(acc[1] * inv + b0.y, 0.01f) * (g0.y * inv_bn) + c0.y;
    o[2] = lrelu(acc[2] * inv + b0.z, 0.01f) * (g0.z * inv_bn) + c0.z;
    o[3] = lrelu(acc[3] * inv + b0.w, 0.01f) * (g0.w * inv_bn) + c0.w;
    o[4] = lrelu(acc[4] * inv + b1.x, 0.01f) * (g1.x * inv_bn) + c1.x;
    o[5] = lrelu(acc[5] * inv + b1.y, 0.01f) * (g1.y * inv_bn) + c1.y;
    o[6] = lrelu(acc[6] * inv + b1.z, 0.01f) * (g1.z * inv_bn) + c1.z;
    o[7] = lrelu(acc[7] * inv + b1.w, 0.01f) * (g1.w * inv_bn) + c1.w;
    uint4 p;
    p.x = pack_half2(o[0], o[1]); p.y = pack_half2(o[2], o[3]);
    p.z = pack_half2(o[4], o[5]); p.w = pack_half2(o[6], o[7]);
    ((uint4*)xout)[(size_t)node * 32 + lane] = p;

    // fused GAT2 scores
    float4 w0a = ((const float4*)ws2)[2 * lane],       w0b = ((const float4*)ws2)[2 * lane + 1];
    float4 w1a = ((const float4*)ws2)[64 + 2 * lane],  w1b = ((const float4*)ws2)[64 + 2 * lane + 1];
    float ss = o[0] * w0a.x + o[1] * w0a.y + o[2] * w0a.z + o[3] * w0a.w
             + o[4] * w0b.x + o[5] * w0b.y + o[6] * w0b.z + o[7] * w0b.w;
    float sd = o[0] * w1a.x + o[1] * w1a.y + o[2] * w1a.z + o[3] * w1a.w
             + o[4] * w1b.x + o[5] * w1b.y + o[6] * w1b.z + o[7] * w1b.w;
#pragma unroll
    for (int off = 16; off; off >>= 1) {
        ss += __shfl_xor_sync(0xffffffffu, ss, off);
        sd += __shfl_xor_sync(0xffffffffu, sd, off);
    }
    if (lane == 0) { scs2[node] = ss; scd2[node] = sd; }
}

// ---------------- GAT2 aggregation: 16-lane subgroups, 2 edges in flight -----
__global__ void k_gat_agg1(const __half* __restrict__ h, const float* __restrict__ scs,
                           const float* __restrict__ scd_arr,
                           const float* __restrict__ bias,
                           const float* __restrict__ bn_g, const float* __restrict__ bn_b,
                           const int* __restrict__ rowstart, const int* __restrict__ col,
                           __half* __restrict__ xout, int n) {
    int node = blockIdx.x * 8 + (threadIdx.x >> 5);
    int lane = threadIdx.x & 31;
    if (node >= n) return;
    int rs = rowstart[node], re = rowstart[node + 1];
    int sub = lane >> 4, sl = lane & 15;

    float scd0 = scd_arr[node];
    const uint4* hu = (const uint4*)h;          // row = 16 uint4

    float acc[8] = {};
    float ws = 0.f;

#define ACC_E1(e, r)                                                           \
    {                                                                          \
        float wv = __expf(lrelu((e) + scd0, 0.2f));                            \
        float2 f;                                                              \
        f = __half22float2(*(const __half2*)&(r).x); acc[0] += f.x * wv; acc[1] += f.y * wv; \
        f = __half22float2(*(const __half2*)&(r).y); acc[2] += f.x * wv; acc[3] += f.y * wv; \
        f = __half22float2(*(const __half2*)&(r).z); acc[4] += f.x * wv; acc[5] += f.y * wv; \
        f = __half22float2(*(const __half2*)&(r).w); acc[6] += f.x * wv; acc[7] += f.y * wv; \
        ws += wv;                                                              \
    }

    for (int base = rs; base < re; base += 32) {
        int idx = base + lane;
        int ck = col[idx < re ? idx : re - 1];
        int cnt = min(32, re - base);
        int j = 0;
        for (; j + 4 <= cnt; j += 4) {
            int sa = __shfl_sync(0xffffffffu, ck, j + sub);
            int sb = __shfl_sync(0xffffffffu, ck, j + 2 + sub);
            float ea = scs[sa], eb = scs[sb];
            uint4 ra = hu[(size_t)sa * 16 + sl];
            uint4 rb = hu[(size_t)sb * 16 + sl];
            ACC_E1(ea, ra)
            ACC_E1(eb, rb)
        }
        for (; j < cnt; j++) {
            int s = __shfl_sync(0xffffffffu, ck, j);
            if ((j & 1) == sub) {
                float e = scs[s];
                uint4 r = hu[(size_t)s * 16 + sl];
                ACC_E1(e, r)
            }
        }
    }
#undef ACC_E1

#pragma unroll
    for (int i = 0; i < 8; i++) acc[i] += __shfl_xor_sync(0xffffffffu, acc[i], 16);
    ws += __shfl_xor_sync(0xffffffffu, ws, 16);

    float inv = 1.f / ws;
    const float inv_bn = rsqrtf(1.0f + 1e-5f);
    float4 b0 = ((const float4*)bias)[2 * sl],  b1 = ((const float4*)bias)[2 * sl + 1];
    float4 g0 = ((const float4*)bn_g)[2 * sl],  g1 = ((const float4*)bn_g)[2 * sl + 1];
    float4 c0 = ((const float4*)bn_b)[2 * sl],  c1 = ((const float4*)bn_b)[2 * sl + 1];
    float o[8];
    o[0] = lrelu(acc[0] * inv + b0.x, 0.01f) * (g0.x * inv_bn) + c0.x;
    o[1] = lrelu(acc[1] * inv + b0.y, 0.01f) * (g0.y * inv_bn) + c0.y;
    o[2] = lrelu(acc[2] * inv + b0.z, 0.01f) * (g0.z * inv_bn) + c0.z;
    o[3] = lrelu(acc[3] * inv + b0.w, 0.01f) * (g0.w * inv_bn) + c0.w;
    o[4] = lrelu(acc[4] * inv + b1.x, 0.01f) * (g1.x * inv_bn) + c1.x;
    o[5] = lrelu(acc[5] * inv + b1.y, 0.01f) * (g1.y * inv_bn) + c1.y;
    o[6] = lrelu(acc[6] * inv + b1.z, 0.01f) * (g1.z * inv_bn) + c1.z;
    o[7] = lrelu(acc[7] * inv + b1.w, 0.01f) * (g1.w * inv_bn) + c1.w;
    if (sub == 0) {
        uint4 p;
        p.x = pack_half2(o[0], o[1]); p.y = pack_half2(o[2], o[3]);
        p.z = pack_half2(o[4], o[5]); p.w = pack_half2(o[6], o[7]);
        ((uint4*)xout)[(size_t)node * 16 + sl] = p;
    }
}

// ---------------- GCN aggregation: 8-lane subgroups, 4 edges in flight -------
__global__ void k_gcn_agg(const __half* __restrict__ h, const float* __restrict__ dis,
                          const float* __restrict__ bg,
                          const int* __restrict__ rowstart, const int* __restrict__ col,
                          float* __restrict__ xout, int n) {
    int node = blockIdx.x * 8 + (threadIdx.x >> 5);
    int lane = threadIdx.x & 31;
    if (node >= n) return;
    int rs = rowstart[node], re = rowstart[node + 1];
    int sub = lane >> 3, sl = lane & 7;
    float wi = dis[node];
    const uint4* hu = (const uint4*)h;          // row = 8 uint4

    float acc[8] = {};

#define ACC_G(wv, r)                                                           \
    {                                                                          \
        float2 f;                                                              \
        f = __half22float2(*(const __half2*)&(r).x); acc[0] += f.x * (wv); acc[1] += f.y * (wv); \
        f = __half22float2(*(const __half2*)&(r).y); acc[2] += f.x * (wv); acc[3] += f.y * (wv); \
        f = __half22float2(*(const __half2*)&(r).z); acc[4] += f.x * (wv); acc[5] += f.y * (wv); \
        f = __half22float2(*(const __half2*)&(r).w); acc[6] += f.x * (wv); acc[7] += f.y * (wv); \
    }

    for (int base = rs; base < re; base += 32) {
        int idx = base + lane;
        int ck = col[idx < re ? idx : re - 1];
        int cnt = min(32, re - base);
        int j = 0;
        for (; j + 4 <= cnt; j += 4) {
            int s = __shfl_sync(0xffffffffu, ck, j + sub);
            float w = dis[s] * wi;
            uint4 r = hu[(size_t)s * 8 + sl];
            ACC_G(w, r)
        }
        for (; j < cnt; j++) {
            int s = __shfl_sync(0xffffffffu, ck, j);
            if ((j & 3) == sub) {
                float w = dis[s] * wi;
                uint4 r = hu[(size_t)s * 8 + sl];
                ACC_G(w, r)
            }
        }
    }
#undef ACC_G

#pragma unroll
    for (int i = 0; i < 8; i++) {
        acc[i] += __shfl_xor_sync(0xffffffffu, acc[i], 8);
        acc[i] += __shfl_xor_sync(0xffffffffu, acc[i], 16);
    }

    if (sub == 0) {
        float4 bg0 = ((const float4*)bg)[2 * sl], bg1 = ((const float4*)bg)[2 * sl + 1];
        float4 o0, o1;
        o0.x = lrelu(acc[0] + bg0.x, 0.01f); o0.y = lrelu(acc[1] + bg0.y, 0.01f);
        o0.z = lrelu(acc[2] + bg0.z, 0.01f); o0.w = lrelu(acc[3] + bg0.w, 0.01f);
        o1.x = lrelu(acc[4] + bg1.x, 0.01f); o1.y = lrelu(acc[5] + bg1.y, 0.01f);
        o1.z = lrelu(acc[6] + bg1.z, 0.01f); o1.w = lrelu(acc[7] + bg1.w, 0.01f);
        ((float4*)xout)[(size_t)node * 16 + 2 * sl]     = o0;
        ((float4*)xout)[(size_t)node * 16 + 2 * sl + 1] = o1;
    }
}

// ---------------- fused pool (segment sum) + MLP ------------------------------
__global__ void __launch_bounds__(128) k_pool_mlp(const float* __restrict__ x3,
                                                  const int* __restrict__ batch,
                                                  const float* __restrict__ l1W,
                                                  const float* __restrict__ l1b,
                                                  const float* __restrict__ g3,
                                                  const float* __restrict__ b3,
                                                  const float* __restrict__ l2W,
                                                  const float* __restrict__ l2b,
                                                  float* __restrict__ out) {
    int b = blockIdx.x;
    int t = threadIdx.x;
    __shared__ int seg[2];
    __shared__ float sp2[2][64];
    __shared__ float spool[64];
    __shared__ float sy[128];

    if (t < 2) seg[t] = lbound(batch, Nn, b + t);
    __syncthreads();
    int lo = seg[0], hi = seg[1];

    int ch = t & 63, half = t >> 6;
    float s = 0.f;
    for (int node = lo + half; node < hi; node += 2)
        s += x3[(size_t)node * D3 + ch];
    sp2[half][ch] = s;
    __syncthreads();
    if (t < 64) {
        float cnt = fmaxf((float)(hi - lo), 1.f);
        spool[t] = (sp2[0][t] + sp2[1][t]) / cnt;
    }
    __syncthreads();

    float v = l1b[t];
#pragma unroll
    for (int k = 0; k < 64; k++) v += spool[k] * l1W[k * 128 + t];
    v = v * (g3[t] * rsqrtf(1.0f + 1e-5f)) + b3[t];
    v = lrelu(v, 0.01f);
    sy[t] = v;
    __syncthreads();
    if (t < NCc) {
        float o = l2b[t];
#pragma unroll
        for (int k = 0; k < 128; k++) o += sy[k] * l2W[k * NCc + t];
        out[b * NCc + t] = o;
    }
}

// ---------------- launch -----------------------------------------------------
extern "C" void kernel_launch(void* const* d_in, const int* in_sizes, int n_in,
                              void* d_out, int out_size) {
    const float* x      = (const float*)d_in[0];
    const int*   ei     = (const int*)d_in[1];
    const int*   batch  = (const int*)d_in[2];
    const float* W1     = (const float*)d_in[3];
    const float* a_src1 = (const float*)d_in[4];
    const float* a_dst1 = (const float*)d_in[5];
    const float* b1     = (const float*)d_in[6];
    const float* W2     = (const float*)d_in[7];
    const float* a_src2 = (const float*)d_in[8];
    const float* a_dst2 = (const float*)d_in[9];
    const float* b2     = (const float*)d_in[10];
    const float* Wg     = (const float*)d_in[11];
    const float* bg     = (const float*)d_in[12];
    const float* bn1g   = (const float*)d_in[13];
    const float* bn1b   = (const float*)d_in[14];
    const float* bn2g   = (const float*)d_in[15];
    const float* bn2b   = (const float*)d_in[16];
    const float* bn3g   = (const float*)d_in[17];
    const float* bn3b   = (const float*)d_in[18];
    const float* l1W    = (const float*)d_in[19];
    const float* l1b    = (const float*)d_in[20];
    const float* l2W    = (const float*)d_in[21];
    const float* l2b    = (const float*)d_in[22];
    float* out = (float*)d_out;

    int *deg, *rowstart, *cursor, *col, *partials;
    __half *h1, *h2, *h3, *x1, *x2;
    float *x3, *scs1, *scd1, *scs2, *scd2, *dis, *ws2;
    cudaGetSymbolAddress((void**)&deg, g_deg);
    cudaGetSymbolAddress((void**)&rowstart, g_rowstart);
    cudaGetSymbolAddress((void**)&cursor, g_cursor);
    cudaGetSymbolAddress((void**)&col, g_col);
    cudaGetSymbolAddress((void**)&partials, g_partials);
    cudaGetSymbolAddress((void**)&h1, g_h1);
    cudaGetSymbolAddress((void**)&x1, g_x1);
    cudaGetSymbolAddress((void**)&h2, g_h2);
    cudaGetSymbolAddress((void**)&x2, g_x2);
    cudaGetSymbolAddress((void**)&h3, g_h3);
    cudaGetSymbolAddress((void**)&x3, g_x3);
    cudaGetSymbolAddress((void**)&scs1, g_scs1);
    cudaGetSymbolAddress((void**)&scd1, g_scd1);
    cudaGetSymbolAddress((void**)&scs2, g_scs2);
    cudaGetSymbolAddress((void**)&scd2, g_scd2);
    cudaGetSymbolAddress((void**)&dis, g_dis);
    cudaGetSymbolAddress((void**)&ws2, g_ws2);

    const int* src = ei;
    const int* dst = ei + Ee;

    static cudaStream_t s2 = nullptr;
    static cudaEvent_t evFork = nullptr, evJoin = nullptr;
    if (!s2) {
        cudaStreamCreateWithFlags(&s2, cudaStreamNonBlocking);
        cudaEventCreateWithFlags(&evFork, cudaEventDisableTiming);
        cudaEventCreateWithFlags(&evJoin, cudaEventDisableTiming);
    }

    // ---- fork ----
    cudaEventRecord(evFork, 0);
    cudaStreamWaitEvent(s2, evFork, 0);

    // s2: CSR chain
    k_init_deg_prep<<<(Nn + 255) / 256, 256, 0, s2>>>(deg, Nn, W2, a_src2, a_dst2, ws2);
    k_deg_scatter<<<(Ee + 255) / 256, 256, 0, s2>>>(dst, deg, Ee);
    k_scan_block<<<NB_SCAN, 1024, 0, s2>>>(deg, rowstart, partials, Nn);
    k_scan_partials<<<1, 64, 0, s2>>>(partials, rowstart, NB_SCAN, Nn);
    k_scan_finalize_fill<<<NB_SCAN, 1024, 0, s2>>>(deg, rowstart, partials, col, cursor, dis, Nn);
    k_scatter_edges<<<(Ee + 255) / 256, 256, 0, s2>>>(src, dst, cursor, col, Ee);
    cudaEventRecord(evJoin, s2);

    // s0: GEMM1 (+fused GAT1 scores, atomic-free -> no zero-fill needed)
    k_gemm_f16<float><<<dim3((Nn + 127) / 128, D1 / 64), 256>>>(
        x, W1, h1, Nn, D1, Fdim, a_src1, a_dst1, scs1, scd1);

    cudaStreamWaitEvent(0, evJoin, 0);

    // ---- GAT layer 1 aggregation (also emits GAT2 scores) ----
    k_gat_agg4<<<(Nn + 7) / 8, 256>>>(h1, scs1, scd1, b1, bn1g, bn1b,
                                      rowstart, col, ws2, x1, scs2, scd2, Nn);

    // ---- GAT layer 2: 256 -> 1 head x 128 ----
    k_gemm_f16<__half><<<dim3((Nn + 127) / 128, D2 / 64), 256>>>(
        x1, W2, h2, Nn, D2, D1, nullptr, nullptr, nullptr, nullptr);
    k_gat_agg1<<<(Nn + 7) / 8, 256>>>(h2, scs2, scd2, b2, bn2g, bn2b,
                                      rowstart, col, x2, Nn);

    // ---- GCN: 128 -> 64 ----
    k_gemm_f16<__half><<<dim3((Nn + 127) / 128, D3 / 64), 256>>>(
        x2, Wg, h3, Nn, D3, D2, nullptr, nullptr, nullptr, nullptr);
    k_gcn_agg<<<(Nn + 7) / 8, 256>>>(h3, dis, bg, rowstart, col, x3, Nn);

    // ---- fused global mean pool + MLP head ----
    k_pool_mlp<<<Bb, 128>>>(x3, batch, l1W, l1b, bn3g, bn3b, l2W, l2b, out);
}